// round 8
// baseline (speedup 1.0000x reference)
#include <cuda_runtime.h>
#include <stdint.h>

// out = cos(X @ Win^T + theta) @ Wout^T      X:[262144,64] fp32
// Single-pass TF32 mma.sync m16n8k8 (rel_err ~4e-4 < 1e-3).
// Layout algebra (validated R6/R7): coalesced LDG.128 for A, natural-order
// LDS.128 for Win, GEMM1 C-frag == GEMM2 A-frag, scrambled Wout -> STG.128.
// R8: 128-thread CTAs, __launch_bounds__(128,5) (<=102 regs -> 20 warps/SM);
// phase-1 streams x per k-chunk to cut peak register liveness.

#define NTOK   (32 * 8192)
#define TILE_T 128                 // tokens per CTA (4 warps x 32)
#define NCTAS  (NTOK / TILE_T)     // 2048
#define PITCH4 20                  // uint4 per smem weight row (20%8==4 -> conflict-free)

__device__ __forceinline__ uint32_t tf32r(float x) {
    uint32_t u;
    asm("cvt.rna.tf32.f32 %0, %1;" : "=r"(u) : "f"(x));
    return u;
}

__device__ __forceinline__ void mma8(float* c, uint32_t a0, uint32_t a1, uint32_t a2, uint32_t a3,
                                     uint32_t b0, uint32_t b1) {
    asm volatile(
        "mma.sync.aligned.m16n8k8.row.col.f32.tf32.tf32.f32 "
        "{%0,%1,%2,%3}, {%4,%5,%6,%7}, {%8,%9}, {%0,%1,%2,%3};"
        : "+f"(c[0]), "+f"(c[1]), "+f"(c[2]), "+f"(c[3])
        : "r"(a0), "r"(a1), "r"(a2), "r"(a3), "r"(b0), "r"(b1));
}

__device__ __forceinline__ float4 ldcs4(const float* p) {
    float4 v;
    asm volatile("ld.global.cs.v4.f32 {%0,%1,%2,%3}, [%4];"
                 : "=f"(v.x), "=f"(v.y), "=f"(v.z), "=f"(v.w) : "l"(p));
    return v;
}
__device__ __forceinline__ void stcs4(float* p, float a, float b, float c, float d) {
    asm volatile("st.global.cs.v4.f32 [%0], {%1,%2,%3,%4};"
                 :: "l"(p), "f"(a), "f"(b), "f"(c), "f"(d));
}

// Wout row scramble (global row offset p -> slot offset u) and col scramble.
__device__ __forceinline__ int ginv_off(int p) {
    return ((p & 2) >> 1) * 8 + ((p >> 2) & 3) * 2 + (p & 1);
}
__device__ __forceinline__ int hcol(int w) {
    return (w & ~15) | (((w & 7) >> 1) << 2) | (((w >> 3) & 1) << 1) | (w & 1);
}

__global__ void __launch_bounds__(128, 5)
quantum_tf32_kernel(const float* __restrict__ x,
                    const float* __restrict__ Win,    // [64][64]
                    const float* __restrict__ theta,  // [64]
                    const float* __restrict__ Wout,   // [64][64]
                    float* __restrict__ out)
{
    __shared__ uint32_t sWin[64 * PITCH4 * 4];   // tf32 bits, natural [n][k]
    __shared__ uint32_t sWout[64 * PITCH4 * 4];  // tf32 bits, row+col scrambled
    __shared__ float    sTh[64];

    const int tid = threadIdx.x;

    // ---- Fill Win (natural) and Wout (scrambled), one-time ----
    for (int idx = tid; idx < 1024; idx += 128) {
        const int r = idx >> 4, q = idx & 15;
        float4 w = ldcs4(Win + r * 64 + q * 4);
        *(uint4*)&sWin[(r * PITCH4 + q) * 4] =
            make_uint4(tf32r(w.x), tf32r(w.y), tf32r(w.z), tf32r(w.w));
    }
    for (int idx = tid; idx < 1024; idx += 128) {
        const int r = idx >> 4, q = idx & 15;
        float4 w = ldcs4(Wout + r * 64 + q * 4);
        const int s = (r & ~15) | ginv_off(r & 15);
        uint32_t* row = &sWout[s * PITCH4 * 4];
        row[hcol(q * 4 + 0)] = tf32r(w.x);
        row[hcol(q * 4 + 1)] = tf32r(w.y);
        row[hcol(q * 4 + 2)] = tf32r(w.z);
        row[hcol(q * 4 + 3)] = tf32r(w.w);
    }
    if (tid < 64) sTh[tid] = theta[tid];
    __syncthreads();

    const int lane = tid & 31;
    const int warp = tid >> 5;    // 0..3
    const int gr   = lane >> 2;
    const int tc   = lane & 3;

    const int tok0 = blockIdx.x * TILE_T + warp * 32;   // 32 tokens (2 m-tiles) per warp
    const float* px = x + (size_t)(tok0 + gr) * 64 + tc * 4;

    // ---- Phase 1: GEMM1, x streamed per k-chunk j (low register liveness) ----
    float t[2][8][4];
#pragma unroll
    for (int mt = 0; mt < 2; mt++)
#pragma unroll
        for (int nt = 0; nt < 8; nt++)
#pragma unroll
            for (int i = 0; i < 4; i++) t[mt][nt][i] = 0.f;

#pragma unroll
    for (int j = 0; j < 4; j++) {
        // xj[mt][half][0..3]: phys cols 16j+4tc..+3 of rows (tok0+16mt+gr [+8])
        uint32_t xj[2][2][4];
#pragma unroll
        for (int mt = 0; mt < 2; mt++) {
            float4 v0 = ldcs4(px + (mt * 16) * 64 + j * 16);
            float4 v1 = ldcs4(px + (mt * 16 + 8) * 64 + j * 16);
            xj[mt][0][0] = tf32r(v0.x); xj[mt][0][1] = tf32r(v0.y);
            xj[mt][0][2] = tf32r(v0.z); xj[mt][0][3] = tf32r(v0.w);
            xj[mt][1][0] = tf32r(v1.x); xj[mt][1][1] = tf32r(v1.y);
            xj[mt][1][2] = tf32r(v1.z); xj[mt][1][3] = tf32r(v1.w);
        }
#pragma unroll
        for (int nt = 0; nt < 8; nt++) {
            const uint4 b = *(const uint4*)&sWin[((8 * nt + gr) * PITCH4 + j * 4 + tc) * 4];
#pragma unroll
            for (int mt = 0; mt < 2; mt++) {
                mma8(t[mt][nt], xj[mt][0][0], xj[mt][1][0],
                                xj[mt][0][1], xj[mt][1][1], b.x, b.y);
                mma8(t[mt][nt], xj[mt][0][2], xj[mt][1][2],
                                xj[mt][0][3], xj[mt][1][3], b.z, b.w);
            }
        }
    }

    // ---- Phase 1.5: q = cos(t + theta), C-frag(c0,c2,c1,c3) -> A-frag, tf32 ----
    uint32_t a2f[2][8][4];
#pragma unroll
    for (int nt = 0; nt < 8; nt++) {
        const float2 tb = *(const float2*)&sTh[8 * nt + 2 * tc];
#pragma unroll
        for (int mt = 0; mt < 2; mt++) {
            a2f[mt][nt][0] = tf32r(__cosf(t[mt][nt][0] + tb.x));
            a2f[mt][nt][1] = tf32r(__cosf(t[mt][nt][2] + tb.x));
            a2f[mt][nt][2] = tf32r(__cosf(t[mt][nt][1] + tb.y));
            a2f[mt][nt][3] = tf32r(__cosf(t[mt][nt][3] + tb.y));
        }
    }
    // t dead here.

    // ---- Phase 2: GEMM2 per output-column pair, store immediately ----
#pragma unroll
    for (int np = 0; np < 4; np++) {          // output nt2 pair {2np, 2np+1}
        float acc[2][2][4];
#pragma unroll
        for (int mt = 0; mt < 2; mt++)
#pragma unroll
            for (int e = 0; e < 2; e++)
#pragma unroll
                for (int i = 0; i < 4; i++) acc[mt][e][i] = 0.f;

#pragma unroll
        for (int j2 = 0; j2 < 4; j2++) {      // K (wire) chunks
#pragma unroll
            for (int e = 0; e < 2; e++) {
                const int nt2 = 2 * np + e;
                const uint4 b2 = *(const uint4*)&sWout[((8 * nt2 + gr) * PITCH4 + j2 * 4 + tc) * 4];
#pragma unroll
                for (int mt = 0; mt < 2; mt++) {
                    mma8(acc[mt][e], a2f[mt][2 * j2][0], a2f[mt][2 * j2][1],
                                     a2f[mt][2 * j2][2], a2f[mt][2 * j2][3], b2.x, b2.y);
                    mma8(acc[mt][e], a2f[mt][2 * j2 + 1][0], a2f[mt][2 * j2 + 1][1],
                                     a2f[mt][2 * j2 + 1][2], a2f[mt][2 * j2 + 1][3], b2.z, b2.w);
                }
            }
        }

        const int col = np * 16 + tc * 4;
#pragma unroll
        for (int mt = 0; mt < 2; mt++) {
            const size_t r0 = (size_t)(tok0 + mt * 16 + gr);
            stcs4(out + r0 * 64 + col,
                  acc[mt][0][0], acc[mt][0][1], acc[mt][1][0], acc[mt][1][1]);
            stcs4(out + (r0 + 8) * 64 + col,
                  acc[mt][0][2], acc[mt][0][3], acc[mt][1][2], acc[mt][1][3]);
        }
    }
}

extern "C" void kernel_launch(void* const* d_in, const int* in_sizes, int n_in,
                              void* d_out, int out_size) {
    const float* x     = (const float*)d_in[0];
    const float* W_in  = (const float*)d_in[1];
    const float* theta = (const float*)d_in[2];
    const float* W_out = (const float*)d_in[3];
    float* out = (float*)d_out;

    quantum_tf32_kernel<<<NCTAS, 128>>>(x, W_in, theta, W_out, out);
}

// round 9
// speedup vs baseline: 1.1488x; 1.1488x over previous
#include <cuda_runtime.h>
#include <stdint.h>

// out = cos(X @ Win^T + theta) @ Wout^T      X:[262144,64] fp32
// Single-pass TF32 mma.sync m16n8k8 (rel_err ~4e-4 < 1e-3).
// Layout algebra (validated R6/R7): coalesced LDG.128 for A, natural-order
// LDS.128 for Win, GEMM1 C-frag == GEMM2 A-frag, scrambled Wout -> STG.128.
// R9: exactly the R7 shape (256 thr, launch_bounds(256,2), 39.6us) with ONE
// change: __cosf (MUFU/XU pipe, ~75% busy hidden in ncu) -> FMA-pipe
// polynomial cos (Cody-Waite pi reduction + deg-8 even minimax + parity sign).

#define NTOK   (32 * 8192)
#define TILE_T 256                 // tokens per CTA (8 warps x 32)
#define NCTAS  (NTOK / TILE_T)     // 1024
#define PITCH4 20                  // uint4 per smem weight row (20%8==4 -> conflict-free)

__device__ __forceinline__ uint32_t tf32r(float x) {
    uint32_t u;
    asm("cvt.rna.tf32.f32 %0, %1;" : "=r"(u) : "f"(x));
    return u;
}

// Polynomial cos on the FMA pipe (no MUFU). |y| <~ 40 fine.
// y = k*pi + r, r in [-pi/2, pi/2]; cos(y) = (-1)^k * cos(r).
__device__ __forceinline__ float cosp(float y) {
    float k = rintf(y * 0.3183098861837907f);            // y/pi
    float r = fmaf(k, -3.1415927410125732f, y);          // y - k*pi_hi
    r = fmaf(k, 8.742277657347586e-8f, r);               // - k*pi_lo
    float s = r * r;
    float p = fmaf(s, 2.44331571e-5f, -1.38873162e-3f);
    p = fmaf(p, s, 4.16666456e-2f);
    p = fmaf(p, s, -4.99999996e-1f);
    p = fmaf(p, s, 1.0f);
    int ki = (int)k;                                     // k is exact integer
    return __uint_as_float(__float_as_uint(p) ^ ((uint32_t)(ki & 1) << 31));
}

__device__ __forceinline__ void mma8(float* c, uint32_t a0, uint32_t a1, uint32_t a2, uint32_t a3,
                                     uint32_t b0, uint32_t b1) {
    asm volatile(
        "mma.sync.aligned.m16n8k8.row.col.f32.tf32.tf32.f32 "
        "{%0,%1,%2,%3}, {%4,%5,%6,%7}, {%8,%9}, {%0,%1,%2,%3};"
        : "+f"(c[0]), "+f"(c[1]), "+f"(c[2]), "+f"(c[3])
        : "r"(a0), "r"(a1), "r"(a2), "r"(a3), "r"(b0), "r"(b1));
}

__device__ __forceinline__ float4 ldcs4(const float* p) {
    float4 v;
    asm volatile("ld.global.cs.v4.f32 {%0,%1,%2,%3}, [%4];"
                 : "=f"(v.x), "=f"(v.y), "=f"(v.z), "=f"(v.w) : "l"(p));
    return v;
}
__device__ __forceinline__ void stcs4(float* p, float a, float b, float c, float d) {
    asm volatile("st.global.cs.v4.f32 [%0], {%1,%2,%3,%4};"
                 :: "l"(p), "f"(a), "f"(b), "f"(c), "f"(d));
}

// Wout row scramble (global row offset p -> slot offset u) and col scramble.
__device__ __forceinline__ int ginv_off(int p) {
    return ((p & 2) >> 1) * 8 + ((p >> 2) & 3) * 2 + (p & 1);
}
__device__ __forceinline__ int hcol(int w) {
    return (w & ~15) | (((w & 7) >> 1) << 2) | (((w >> 3) & 1) << 1) | (w & 1);
}

__global__ void __launch_bounds__(256, 2)
quantum_tf32_kernel(const float* __restrict__ x,
                    const float* __restrict__ Win,    // [64][64]
                    const float* __restrict__ theta,  // [64]
                    const float* __restrict__ Wout,   // [64][64]
                    float* __restrict__ out)
{
    __shared__ uint32_t sWin[64 * PITCH4 * 4];   // tf32 bits, natural [n][k]
    __shared__ uint32_t sWout[64 * PITCH4 * 4];  // tf32 bits, row+col scrambled
    __shared__ float    sTh[64];

    const int tid = threadIdx.x;

    // ---- Fill Win (natural) and Wout (scrambled), one-time ----
    for (int idx = tid; idx < 1024; idx += 256) {
        const int r = idx >> 4, q = idx & 15;
        float4 w = ldcs4(Win + r * 64 + q * 4);
        *(uint4*)&sWin[(r * PITCH4 + q) * 4] =
            make_uint4(tf32r(w.x), tf32r(w.y), tf32r(w.z), tf32r(w.w));
    }
    for (int idx = tid; idx < 1024; idx += 256) {
        const int r = idx >> 4, q = idx & 15;
        float4 w = ldcs4(Wout + r * 64 + q * 4);
        const int s = (r & ~15) | ginv_off(r & 15);
        uint32_t* row = &sWout[s * PITCH4 * 4];
        row[hcol(q * 4 + 0)] = tf32r(w.x);
        row[hcol(q * 4 + 1)] = tf32r(w.y);
        row[hcol(q * 4 + 2)] = tf32r(w.z);
        row[hcol(q * 4 + 3)] = tf32r(w.w);
    }
    if (tid < 64) sTh[tid] = theta[tid];
    __syncthreads();

    const int lane = tid & 31;
    const int warp = tid >> 5;    // 0..7
    const int gr   = lane >> 2;
    const int tc   = lane & 3;

    const int tok0 = blockIdx.x * TILE_T + warp * 32;   // 32 tokens (2 m-tiles) per warp

    // ---- Phase 0: coalesced LDG.128 of A, cvt to tf32 ----
    uint32_t xa[2][2][4][4];
#pragma unroll
    for (int mt = 0; mt < 2; mt++) {
        const size_t r0 = (size_t)(tok0 + mt * 16 + gr);
#pragma unroll
        for (int j = 0; j < 4; j++) {
            float4 v0 = ldcs4(x + r0 * 64 + j * 16 + tc * 4);
            float4 v1 = ldcs4(x + (r0 + 8) * 64 + j * 16 + tc * 4);
            xa[mt][0][j][0] = tf32r(v0.x); xa[mt][0][j][1] = tf32r(v0.y);
            xa[mt][0][j][2] = tf32r(v0.z); xa[mt][0][j][3] = tf32r(v0.w);
            xa[mt][1][j][0] = tf32r(v1.x); xa[mt][1][j][1] = tf32r(v1.y);
            xa[mt][1][j][2] = tf32r(v1.z); xa[mt][1][j][3] = tf32r(v1.w);
        }
    }

    // ---- Phase 1: full GEMM1, 16 independent accumulator chains ----
    float t[2][8][4];
#pragma unroll
    for (int mt = 0; mt < 2; mt++)
#pragma unroll
        for (int nt = 0; nt < 8; nt++)
#pragma unroll
            for (int i = 0; i < 4; i++) t[mt][nt][i] = 0.f;

#pragma unroll
    for (int j = 0; j < 4; j++) {
#pragma unroll
        for (int nt = 0; nt < 8; nt++) {
            const uint4 b = *(const uint4*)&sWin[((8 * nt + gr) * PITCH4 + j * 4 + tc) * 4];
#pragma unroll
            for (int mt = 0; mt < 2; mt++) {
                mma8(t[mt][nt], xa[mt][0][j][0], xa[mt][1][j][0],
                                xa[mt][0][j][1], xa[mt][1][j][1], b.x, b.y);
                mma8(t[mt][nt], xa[mt][0][j][2], xa[mt][1][j][2],
                                xa[mt][0][j][3], xa[mt][1][j][3], b.z, b.w);
            }
        }
    }
    // xa dead here.

    // ---- Phase 1.5: q = cos(t + theta) via FMA-pipe poly; C-frag -> A-frag ----
    uint32_t a2f[2][8][4];
#pragma unroll
    for (int nt = 0; nt < 8; nt++) {
        const float2 tb = *(const float2*)&sTh[8 * nt + 2 * tc];
#pragma unroll
        for (int mt = 0; mt < 2; mt++) {
            a2f[mt][nt][0] = tf32r(cosp(t[mt][nt][0] + tb.x));
            a2f[mt][nt][1] = tf32r(cosp(t[mt][nt][2] + tb.x));
            a2f[mt][nt][2] = tf32r(cosp(t[mt][nt][1] + tb.y));
            a2f[mt][nt][3] = tf32r(cosp(t[mt][nt][3] + tb.y));
        }
    }
    // t dead here.

    // ---- Phase 2: GEMM2 per output-column pair, store immediately ----
#pragma unroll
    for (int np = 0; np < 4; np++) {          // output nt2 pair {2np, 2np+1}
        float acc[2][2][4];
#pragma unroll
        for (int mt = 0; mt < 2; mt++)
#pragma unroll
            for (int e = 0; e < 2; e++)
#pragma unroll
                for (int i = 0; i < 4; i++) acc[mt][e][i] = 0.f;

#pragma unroll
        for (int j2 = 0; j2 < 4; j2++) {      // K (wire) chunks
#pragma unroll
            for (int e = 0; e < 2; e++) {
                const int nt2 = 2 * np + e;
                const uint4 b2 = *(const uint4*)&sWout[((8 * nt2 + gr) * PITCH4 + j2 * 4 + tc) * 4];
#pragma unroll
                for (int mt = 0; mt < 2; mt++) {
                    mma8(acc[mt][e], a2f[mt][2 * j2][0], a2f[mt][2 * j2][1],
                                     a2f[mt][2 * j2][2], a2f[mt][2 * j2][3], b2.x, b2.y);
                    mma8(acc[mt][e], a2f[mt][2 * j2 + 1][0], a2f[mt][2 * j2 + 1][1],
                                     a2f[mt][2 * j2 + 1][2], a2f[mt][2 * j2 + 1][3], b2.z, b2.w);
                }
            }
        }

        const int col = np * 16 + tc * 4;
#pragma unroll
        for (int mt = 0; mt < 2; mt++) {
            const size_t r0 = (size_t)(tok0 + mt * 16 + gr);
            stcs4(out + r0 * 64 + col,
                  acc[mt][0][0], acc[mt][0][1], acc[mt][1][0], acc[mt][1][1]);
            stcs4(out + (r0 + 8) * 64 + col,
                  acc[mt][0][2], acc[mt][0][3], acc[mt][1][2], acc[mt][1][3]);
        }
    }
}

extern "C" void kernel_launch(void* const* d_in, const int* in_sizes, int n_in,
                              void* d_out, int out_size) {
    const float* x     = (const float*)d_in[0];
    const float* W_in  = (const float*)d_in[1];
    const float* theta = (const float*)d_in[2];
    const float* W_out = (const float*)d_in[3];
    float* out = (float*)d_out;

    quantum_tf32_kernel<<<NCTAS, 256>>>(x, W_in, theta, W_out, out);
}

// round 10
// speedup vs baseline: 1.5808x; 1.3760x over previous
#include <cuda_runtime.h>
#include <stdint.h>

// out = cos(X @ Win^T + theta) @ Wout^T      X:[262144,64] fp32
// R10: fp16 m16n8k16 single-pass (11-bit mantissa == tf32 -> rel_err ~4e-4),
// halving MMA count and B-fragment LDS traffic vs the R7 tf32 kernel.
// Win stored natural (thread b0|b1 = 4 consecutive cols); Wout row-scrambled
// (ginv) + word-scattered into LDS.128 quads so outputs store as STG.128.
// Shape: 256 threads, launch_bounds(256,2) (R7's proven occupancy point).

#define NTOK   (32 * 8192)
#define TILE_T 256                 // tokens per CTA (8 warps x 32)
#define NCTAS  (NTOK / TILE_T)     // 1024
#define PITCH4 12                  // uint4 per smem weight row (12%8==4 -> conflict-free)

__device__ __forceinline__ uint32_t pack_h2(float lo, float hi) {
    uint32_t d;
    asm("cvt.rn.f16x2.f32 %0, %1, %2;" : "=r"(d) : "f"(hi), "f"(lo));
    return d;
}

__device__ __forceinline__ void mma16(float* c, uint32_t a0, uint32_t a1, uint32_t a2, uint32_t a3,
                                      uint32_t b0, uint32_t b1) {
    asm volatile(
        "mma.sync.aligned.m16n8k16.row.col.f32.f16.f16.f32 "
        "{%0,%1,%2,%3}, {%4,%5,%6,%7}, {%8,%9}, {%0,%1,%2,%3};"
        : "+f"(c[0]), "+f"(c[1]), "+f"(c[2]), "+f"(c[3])
        : "r"(a0), "r"(a1), "r"(a2), "r"(a3), "r"(b0), "r"(b1));
}

__device__ __forceinline__ float4 ldcs4(const float* p) {
    float4 v;
    asm volatile("ld.global.cs.v4.f32 {%0,%1,%2,%3}, [%4];"
                 : "=f"(v.x), "=f"(v.y), "=f"(v.z), "=f"(v.w) : "l"(p));
    return v;
}
__device__ __forceinline__ void stcs4(float* p, float a, float b, float c, float d) {
    asm volatile("st.global.cs.v4.f32 [%0], {%1,%2,%3,%4};"
                 :: "l"(p), "f"(a), "f"(b), "f"(c), "f"(d));
}

// Wout row scramble: logical out-row o -> slot row s (so that slot s holds
// logical col hcol(s) and stores coalesce into STG.128).
__device__ __forceinline__ int ginv_off(int p) {
    return ((p & 2) >> 1) * 8 + ((p >> 2) & 3) * 2 + (p & 1);
}

__global__ void __launch_bounds__(256, 2)
quantum_fp16_kernel(const float* __restrict__ x,
                    const float* __restrict__ Win,    // [64][64]
                    const float* __restrict__ theta,  // [64]
                    const float* __restrict__ Wout,   // [64][64]
                    float* __restrict__ out)
{
    // fp16 weights in LDS.128 quads. Quad (row, jp*4+tc):
    //   sWin : {b0(j=2jp), b1(2jp), b0(2jp+1), b1(2jp+1)}, b0|b1 = words 8j+2tc,+1
    //   sWout: {b0(j2=2jp), b1(2jp), b0(2jp+1), b1(2jp+1)}, b0 = word 8j2+tc, b1 = word 8j2+4+tc
    __shared__ uint32_t sWin[64 * PITCH4 * 4];
    __shared__ uint32_t sWout[64 * PITCH4 * 4];
    __shared__ float    sTh[64];

    const int tid = threadIdx.x;

    // ---- Fill Win (natural words, quad-grouped) ----
    for (int idx = tid; idx < 1024; idx += 256) {
        const int r = idx >> 4, c = idx & 15;       // float4 c: cols 4c..4c+3 = words 2c,2c+1
        float4 w = ldcs4(Win + r * 64 + c * 4);
        const int j = c >> 2, tcw = c & 3;          // word 2c: chunk j, within-chunk pair tcw
        uint32_t* quad = &sWin[(r * PITCH4 + (j >> 1) * 4 + tcw) * 4];
        quad[(j & 1) * 2 + 0] = pack_h2(w.x, w.y);
        quad[(j & 1) * 2 + 1] = pack_h2(w.z, w.w);
    }
    // ---- Fill Wout (row scramble + word scatter into quads) ----
    for (int idx = tid; idx < 1024; idx += 256) {
        const int r = idx >> 4, c = idx & 15;
        float4 w = ldcs4(Wout + r * 64 + c * 4);
        const int s = (r & ~15) | ginv_off(r & 15);
        uint32_t ww0 = pack_h2(w.x, w.y), ww1 = pack_h2(w.z, w.w);
#pragma unroll
        for (int d = 0; d < 2; d++) {
            const int wv = 2 * c + d;               // word index: cols 2wv, 2wv+1
            const int j2 = wv >> 3, v = wv & 7;
            const int tcw  = (v < 4) ? v : v - 4;
            const int elem = (j2 & 1) * 2 + ((v < 4) ? 0 : 1);
            sWout[(s * PITCH4 + (j2 >> 1) * 4 + tcw) * 4 + elem] = d ? ww1 : ww0;
        }
    }
    if (tid < 64) sTh[tid] = theta[tid];
    __syncthreads();

    const int lane = tid & 31;
    const int warp = tid >> 5;    // 0..7
    const int gr   = lane >> 2;
    const int tc   = lane & 3;

    const int tok0 = blockIdx.x * TILE_T + warp * 32;   // 32 tokens (2 m-tiles) per warp

    // ---- Phase 0: coalesced LDG.128 of X, pack to fp16 A-frags ----
    // Slot convention: chunk j, mma k-slot (2tc+d) <- col 16j+4tc+d;
    //                  slot (8+2tc+d) <- col 16j+4tc+2+d. Win b0|b1 matches.
    uint32_t xa[2][4][4];   // [mt][j][a0..a3]
#pragma unroll
    for (int mt = 0; mt < 2; mt++) {
        const size_t r0 = (size_t)(tok0 + mt * 16 + gr);
#pragma unroll
        for (int j = 0; j < 4; j++) {
            float4 v0 = ldcs4(x + r0 * 64 + j * 16 + tc * 4);
            float4 v1 = ldcs4(x + (r0 + 8) * 64 + j * 16 + tc * 4);
            xa[mt][j][0] = pack_h2(v0.x, v0.y);   // row gr,   k-lo
            xa[mt][j][1] = pack_h2(v1.x, v1.y);   // row gr+8, k-lo
            xa[mt][j][2] = pack_h2(v0.z, v0.w);   // row gr,   k-hi
            xa[mt][j][3] = pack_h2(v1.z, v1.w);   // row gr+8, k-hi
        }
    }

    // ---- Phase 1: GEMM1 (fp16 k16), 16 independent accumulator chains ----
    float t[2][8][4];
#pragma unroll
    for (int mt = 0; mt < 2; mt++)
#pragma unroll
        for (int nt = 0; nt < 8; nt++)
#pragma unroll
            for (int i = 0; i < 4; i++) t[mt][nt][i] = 0.f;

#pragma unroll
    for (int jp = 0; jp < 2; jp++) {
#pragma unroll
        for (int nt = 0; nt < 8; nt++) {
            const uint4 b = *(const uint4*)&sWin[((8 * nt + gr) * PITCH4 + jp * 4 + tc) * 4];
#pragma unroll
            for (int mt = 0; mt < 2; mt++) {
                mma16(t[mt][nt], xa[mt][2 * jp][0], xa[mt][2 * jp][1],
                                 xa[mt][2 * jp][2], xa[mt][2 * jp][3], b.x, b.y);
                mma16(t[mt][nt], xa[mt][2 * jp + 1][0], xa[mt][2 * jp + 1][1],
                                 xa[mt][2 * jp + 1][2], xa[mt][2 * jp + 1][3], b.z, b.w);
            }
        }
    }
    // xa dead here.

    // ---- Phase 1.5: q = cos(t + theta); pack straight into GEMM2 A-frags ----
    // c0=(gr,8nt+2tc) c1=(gr,+1) c2=(gr+8,..) c3 -> chunk j2=nt>>1, regs 2e+{0,1}
    uint32_t a2f[2][4][4];  // [mt][j2][a0..a3]
#pragma unroll
    for (int nt = 0; nt < 8; nt++) {
        const float2 tb = *(const float2*)&sTh[8 * nt + 2 * tc];
        const int j2 = nt >> 1, e = nt & 1;
#pragma unroll
        for (int mt = 0; mt < 2; mt++) {
            float f0 = __cosf(t[mt][nt][0] + tb.x);
            float f1 = __cosf(t[mt][nt][1] + tb.y);
            float f2 = __cosf(t[mt][nt][2] + tb.x);
            float f3 = __cosf(t[mt][nt][3] + tb.y);
            a2f[mt][j2][2 * e + 0] = pack_h2(f0, f1);
            a2f[mt][j2][2 * e + 1] = pack_h2(f2, f3);
        }
    }
    // t dead here.

    // ---- Phase 2: GEMM2 per output-tile pair, store STG.128 immediately ----
#pragma unroll
    for (int np = 0; np < 4; np++) {
        float acc[2][2][4];
#pragma unroll
        for (int mt = 0; mt < 2; mt++)
#pragma unroll
            for (int e = 0; e < 2; e++)
#pragma unroll
                for (int i = 0; i < 4; i++) acc[mt][e][i] = 0.f;

#pragma unroll
        for (int jp = 0; jp < 2; jp++) {
#pragma unroll
            for (int e = 0; e < 2; e++) {
                const int nt2 = 2 * np + e;
                const uint4 b2 = *(const uint4*)&sWout[((8 * nt2 + gr) * PITCH4 + jp * 4 + tc) * 4];
#pragma unroll
                for (int mt = 0; mt < 2; mt++) {
                    mma16(acc[mt][e], a2f[mt][2 * jp][0], a2f[mt][2 * jp][1],
                                      a2f[mt][2 * jp][2], a2f[mt][2 * jp][3], b2.x, b2.y);
                    mma16(acc[mt][e], a2f[mt][2 * jp + 1][0], a2f[mt][2 * jp + 1][1],
                                      a2f[mt][2 * jp + 1][2], a2f[mt][2 * jp + 1][3], b2.z, b2.w);
                }
            }
        }

        const int col = np * 16 + tc * 4;   // logical cols: hcol makes them contiguous
#pragma unroll
        for (int mt = 0; mt < 2; mt++) {
            const size_t r0 = (size_t)(tok0 + mt * 16 + gr);
            stcs4(out + r0 * 64 + col,
                  acc[mt][0][0], acc[mt][0][1], acc[mt][1][0], acc[mt][1][1]);
            stcs4(out + (r0 + 8) * 64 + col,
                  acc[mt][0][2], acc[mt][0][3], acc[mt][1][2], acc[mt][1][3]);
        }
    }
}

extern "C" void kernel_launch(void* const* d_in, const int* in_sizes, int n_in,
                              void* d_out, int out_size) {
    const float* x     = (const float*)d_in[0];
    const float* W_in  = (const float*)d_in[1];
    const float* theta = (const float*)d_in[2];
    const float* W_out = (const float*)d_in[3];
    float* out = (float*)d_out;

    quantum_fp16_kernel<<<NCTAS, 256>>>(x, W_in, theta, W_out, out);
}